// round 5
// baseline (speedup 1.0000x reference)
#include <cuda_runtime.h>
#include <cuda_bf16.h>
#include <cstdint>

#define NB   32
#define HW   48
#define DIM  384
#define D3   1152
#define NHE  8
#define HDI  48
#define WSZ  6
#define VTOK 36
#define NM   2048
#define TOK  73728
#define KDIM 384
#define SCALE 0.14433756729740643f

// ---------------- scratch (device globals) ----------------------------------
__device__ __nv_bfloat16 g_x_hi[(size_t)TOK * KDIM];
__device__ __nv_bfloat16 g_x_lo[(size_t)TOK * KDIM];
__device__ __nv_bfloat16 g_wq_hi[(size_t)D3 * KDIM];   // transposed [n][k]
__device__ __nv_bfloat16 g_wq_lo[(size_t)D3 * KDIM];
__device__ __nv_bfloat16 g_wp_hi[(size_t)DIM * KDIM];  // transposed [n][k]
__device__ __nv_bfloat16 g_wp_lo[(size_t)DIM * KDIM];
__device__ float         g_qkv[(size_t)TOK * D3];      // raster pixel order
__device__ __nv_bfloat16 g_att_hi[(size_t)TOK * DIM];  // raster pixel order
__device__ __nv_bfloat16 g_att_lo[(size_t)TOK * DIM];

__device__ __forceinline__ void split2(float v, uint16_t& h, uint16_t& l) {
    __nv_bfloat16 hb = __float2bfloat16_rn(v);
    float r = v - __bfloat162float(hb);
    __nv_bfloat16 lb = __float2bfloat16_rn(r);
    h = __bfloat16_as_ushort(hb);
    l = __bfloat16_as_ushort(lb);
}

// ---------------- prep kernels ----------------------------------------------
__global__ __launch_bounds__(256) void split_x(const float* __restrict__ x) {
    size_t i = (size_t)blockIdx.x * 256 + threadIdx.x;
    float4 v = ((const float4*)x)[i];
    uint16_t h0, h1, h2, h3, l0, l1, l2, l3;
    split2(v.x, h0, l0); split2(v.y, h1, l1);
    split2(v.z, h2, l2); split2(v.w, h3, l3);
    uint2 H, L;
    H.x = (uint32_t)h0 | ((uint32_t)h1 << 16);
    H.y = (uint32_t)h2 | ((uint32_t)h3 << 16);
    L.x = (uint32_t)l0 | ((uint32_t)l1 << 16);
    L.y = (uint32_t)l2 | ((uint32_t)l3 << 16);
    ((uint2*)g_x_hi)[i] = H;
    ((uint2*)g_x_lo)[i] = L;
}

template <int NT>
__global__ __launch_bounds__(256) void split_w(const float* __restrict__ w) {
    int idx = blockIdx.x * 256 + threadIdx.x;       // idx = k*NT + n
    int k = idx / NT, n = idx - k * NT;
    uint16_t h, l;
    split2(w[idx], h, l);
    __nv_bfloat16* wh = (NT == D3) ? g_wq_hi : g_wp_hi;
    __nv_bfloat16* wl = (NT == D3) ? g_wq_lo : g_wp_lo;
    ((uint16_t*)wh)[(size_t)n * KDIM + k] = h;
    ((uint16_t*)wl)[(size_t)n * KDIM + k] = l;
}

// ---------------- bf16-split tensor-core GEMM -------------------------------
// CTA 128x128, 128 threads = 4 warps in 2x2 grid, warp tile 64x64.
// Per k16 per warp: 8KB fragments -> 96 MMAs (85 B/MMA): tensor-bound.
#define SSTRIDE 40        // bf16 per smem row (32 data + 8 pad), conflict-free
#define TILE_B  10240     // 128*40*2 bytes per (tile, precision) plane
#define STAGE_B 40960     // Ah | Al | Bh | Bl

__device__ __forceinline__ void cp16(uint32_t dst, const void* src) {
    asm volatile("cp.async.cg.shared.global [%0], [%1], 16;\n" :: "r"(dst), "l"(src));
}

#define MMA_BF16(d, a, b0, b1)                                                \
    asm volatile(                                                             \
        "mma.sync.aligned.m16n8k16.row.col.f32.bf16.bf16.f32 "                \
        "{%0,%1,%2,%3},{%4,%5,%6,%7},{%8,%9},{%0,%1,%2,%3};"                  \
        : "+f"(d[0]), "+f"(d[1]), "+f"(d[2]), "+f"(d[3])                      \
        : "r"(a[0]), "r"(a[1]), "r"(a[2]), "r"(a[3]), "r"(b0), "r"(b1))

__device__ __forceinline__ void stage_load(
    uint32_t sb, const __nv_bfloat16* __restrict__ Ah, const __nv_bfloat16* __restrict__ Al,
    const __nv_bfloat16* __restrict__ Bh, const __nv_bfloat16* __restrict__ Bl,
    int row0, int col0, int k0, int tid)
{
#pragma unroll
    for (int i = 0; i < 4; i++) {
        int c = tid + i * 128;                      // 0..511
        int r = c >> 2;
        int eo = (c & 3) * 8;
        uint32_t doff = (uint32_t)(r * SSTRIDE + eo) * 2;
        size_t aoff = (size_t)(row0 + r) * KDIM + k0 + eo;
        size_t boff = (size_t)(col0 + r) * KDIM + k0 + eo;
        cp16(sb + 0 * TILE_B + doff, Ah + aoff);
        cp16(sb + 1 * TILE_B + doff, Al + aoff);
        cp16(sb + 2 * TILE_B + doff, Bh + boff);
        cp16(sb + 3 * TILE_B + doff, Bl + boff);
    }
}

// WHICH: 0 = qkv, 1 = proj. Grid: x = column tiles (few), y = row tiles.
template <int WHICH>
__global__ __launch_bounds__(128) void gemm_bf16(const float* __restrict__ bias,
                                                 float* __restrict__ Cout)
{
    constexpr int NT = (WHICH == 0) ? D3 : DIM;
    const __nv_bfloat16* Ah = (WHICH == 0) ? g_x_hi : g_att_hi;
    const __nv_bfloat16* Al = (WHICH == 0) ? g_x_lo : g_att_lo;
    const __nv_bfloat16* Bh = (WHICH == 0) ? g_wq_hi : g_wp_hi;
    const __nv_bfloat16* Bl = (WHICH == 0) ? g_wq_lo : g_wp_lo;
    float* C = (WHICH == 0) ? g_qkv : Cout;

    extern __shared__ char sm[];
    const int tid  = threadIdx.x;
    const int row0 = blockIdx.y * 128;
    const int col0 = blockIdx.x * 128;
    const int lane = tid & 31, warp = tid >> 5;
    const int wm = warp & 1, wn = warp >> 1;      // 2x2 warp grid, warp tile 64x64
    const int g = lane >> 2, t = lane & 3;

    uint32_t sbase = (uint32_t)__cvta_generic_to_shared(sm);

    float acc[4][8][4] = {};

    stage_load(sbase, Ah, Al, Bh, Bl, row0, col0, 0, tid);
    asm volatile("cp.async.commit_group;\n" ::: "memory");

    for (int kt = 0; kt < 12; kt++) {
        if (kt < 11) {
            stage_load(sbase + ((kt + 1) & 1) * STAGE_B, Ah, Al, Bh, Bl,
                       row0, col0, (kt + 1) * 32, tid);
            asm volatile("cp.async.commit_group;\n" ::: "memory");
            asm volatile("cp.async.wait_group 1;\n" ::: "memory");
        } else {
            asm volatile("cp.async.wait_group 0;\n" ::: "memory");
        }
        __syncthreads();

        const __nv_bfloat16* sA_h = (const __nv_bfloat16*)(sm + (kt & 1) * STAGE_B);
        const __nv_bfloat16* sA_l = sA_h + 5120;
        const __nv_bfloat16* sB_h = sA_h + 10240;
        const __nv_bfloat16* sB_l = sA_h + 15360;

#pragma unroll
        for (int k16 = 0; k16 < 32; k16 += 16) {
            uint32_t ah[4][4], al[4][4], bh[8][2], bl[8][2];
#pragma unroll
            for (int mt = 0; mt < 4; mt++) {
                int e = (wm * 64 + mt * 16 + g) * SSTRIDE + k16 + t * 2;
                ah[mt][0] = *(const uint32_t*)(sA_h + e);
                ah[mt][1] = *(const uint32_t*)(sA_h + e + 8 * SSTRIDE);
                ah[mt][2] = *(const uint32_t*)(sA_h + e + 8);
                ah[mt][3] = *(const uint32_t*)(sA_h + e + 8 * SSTRIDE + 8);
                al[mt][0] = *(const uint32_t*)(sA_l + e);
                al[mt][1] = *(const uint32_t*)(sA_l + e + 8 * SSTRIDE);
                al[mt][2] = *(const uint32_t*)(sA_l + e + 8);
                al[mt][3] = *(const uint32_t*)(sA_l + e + 8 * SSTRIDE + 8);
            }
#pragma unroll
            for (int nt = 0; nt < 8; nt++) {
                int e = (wn * 64 + nt * 8 + g) * SSTRIDE + k16 + t * 2;
                bh[nt][0] = *(const uint32_t*)(sB_h + e);
                bh[nt][1] = *(const uint32_t*)(sB_h + e + 8);
                bl[nt][0] = *(const uint32_t*)(sB_l + e);
                bl[nt][1] = *(const uint32_t*)(sB_l + e + 8);
            }
            // hi*hi, hi*lo, lo*hi — 32 independent MMAs per pass
#pragma unroll
            for (int mt = 0; mt < 4; mt++)
#pragma unroll
                for (int nt = 0; nt < 8; nt++)
                    MMA_BF16(acc[mt][nt], ah[mt], bh[nt][0], bh[nt][1]);
#pragma unroll
            for (int mt = 0; mt < 4; mt++)
#pragma unroll
                for (int nt = 0; nt < 8; nt++)
                    MMA_BF16(acc[mt][nt], ah[mt], bl[nt][0], bl[nt][1]);
#pragma unroll
            for (int mt = 0; mt < 4; mt++)
#pragma unroll
                for (int nt = 0; nt < 8; nt++)
                    MMA_BF16(acc[mt][nt], al[mt], bh[nt][0], bh[nt][1]);
        }
        __syncthreads();
    }

    // epilogue: bias + fp32 store
#pragma unroll
    for (int nt = 0; nt < 8; nt++) {
        int ce = col0 + wn * 64 + nt * 8 + t * 2;
        float b0 = bias[ce], b1 = bias[ce + 1];
#pragma unroll
        for (int mt = 0; mt < 4; mt++) {
            int re = row0 + wm * 64 + mt * 16 + g;
            float* p0 = C + (size_t)re * NT + ce;
            p0[0] = acc[mt][nt][0] + b0;
            p0[1] = acc[mt][nt][1] + b1;
            float* p1 = p0 + (size_t)8 * NT;
            p1[0] = acc[mt][nt][2] + b0;
            p1[1] = acc[mt][nt][3] + b1;
        }
    }
}

// ---------------- attention (identical to R2 known-good) --------------------
__global__ __launch_bounds__(128) void attn_kernel() {
    const int m    = blockIdx.x;
    const int head = blockIdx.y;
    __shared__ float qs[VTOK][HDI];
    __shared__ float ks[VTOK][HDI];
    __shared__ float vs[VTOK][HDI];
    __shared__ float ss[VTOK][VTOK];
    __shared__ int   rid[VTOK];
    __shared__ int   pix[VTOK];

    const int tid = threadIdx.x;
    if (tid < VTOK) {
        int wi = m & 63;
        int i  = (wi >> 3) * WSZ + tid / WSZ;
        int j  = (wi & 7)  * WSZ + tid % WSZ;
        rid[tid] = ((i < 45) ? 2 : 0) + ((j < 45) ? 1 : 0);
        int b = m >> 6;
        int h = (i < 45) ? i + 3 : i - 45;
        int w = (j < 45) ? j + 3 : j - 45;
        pix[tid] = (b * HW + h) * HW + w;
    }
    __syncthreads();

    for (int idx = tid; idx < 3 * VTOK * 12; idx += 128) {
        int t3  = idx / (VTOK * 12);
        int rem = idx - t3 * (VTOK * 12);
        int r = rem / 12;
        int c = rem - r * 12;
        float4 f = *(const float4*)(g_qkv + (size_t)pix[r] * D3 + t3 * DIM + head * HDI + c * 4);
        float* dst = (t3 == 0) ? &qs[r][c * 4] : (t3 == 1) ? &ks[r][c * 4] : &vs[r][c * 4];
        *(float4*)dst = f;
    }
    __syncthreads();

    for (int idx = tid; idx < VTOK * VTOK; idx += 128) {
        int v = idx / VTOK;
        int u = idx - v * VTOK;
        float acc = 0.f;
#pragma unroll
        for (int c = 0; c < 12; c++) {
            float4 a = *(float4*)&qs[v][c * 4];
            float4 b = *(float4*)&ks[u][c * 4];
            acc += a.x * b.x + a.y * b.y + a.z * b.z + a.w * b.w;
        }
        ss[v][u] = (rid[v] == rid[u]) ? acc * SCALE : -1e30f;
    }
    __syncthreads();

    if (tid < VTOK) {
        float mx = -1e30f;
#pragma unroll
        for (int u = 0; u < VTOK; u++) mx = fmaxf(mx, ss[tid][u]);
        float sum = 0.f;
#pragma unroll
        for (int u = 0; u < VTOK; u++) {
            float e = __expf(ss[tid][u] - mx);
            ss[tid][u] = e;
            sum += e;
        }
        float inv = 1.f / sum;
#pragma unroll
        for (int u = 0; u < VTOK; u++) ss[tid][u] *= inv;
    }
    __syncthreads();

    for (int idx = tid; idx < VTOK * 12; idx += 128) {
        int v = idx / 12;
        int c = idx - v * 12;
        float4 acc = make_float4(0.f, 0.f, 0.f, 0.f);
#pragma unroll
        for (int u = 0; u < VTOK; u++) {
            float  p  = ss[v][u];
            float4 vv = *(float4*)&vs[u][c * 4];
            acc.x += p * vv.x; acc.y += p * vv.y;
            acc.z += p * vv.z; acc.w += p * vv.w;
        }
        size_t o = (size_t)pix[v] * DIM + head * HDI + c * 4;
        uint16_t h0, h1, h2, h3, l0, l1, l2, l3;
        split2(acc.x, h0, l0); split2(acc.y, h1, l1);
        split2(acc.z, h2, l2); split2(acc.w, h3, l3);
        uint2 H, L;
        H.x = (uint32_t)h0 | ((uint32_t)h1 << 16);
        H.y = (uint32_t)h2 | ((uint32_t)h3 << 16);
        L.x = (uint32_t)l0 | ((uint32_t)l1 << 16);
        L.y = (uint32_t)l2 | ((uint32_t)l3 << 16);
        *(uint2*)(g_att_hi + o) = H;
        *(uint2*)(g_att_lo + o) = L;
    }
}

extern "C" void kernel_launch(void* const* d_in, const int* in_sizes, int n_in,
                              void* d_out, int out_size) {
    const float* x      = (const float*)d_in[0];
    const float* w_qkv  = (const float*)d_in[1];
    const float* b_qkv  = (const float*)d_in[2];
    const float* w_proj = (const float*)d_in[3];
    const float* b_proj = (const float*)d_in[4];
    float* out = (float*)d_out;

    cudaFuncSetAttribute(gemm_bf16<0>, cudaFuncAttributeMaxDynamicSharedMemorySize, 2 * STAGE_B);
    cudaFuncSetAttribute(gemm_bf16<1>, cudaFuncAttributeMaxDynamicSharedMemorySize, 2 * STAGE_B);

    split_x<<<27648, 256>>>(x);
    split_w<D3><<<(KDIM * D3) / 256, 256>>>(w_qkv);
    split_w<DIM><<<(KDIM * DIM) / 256, 256>>>(w_proj);

    // x = column tiles (few, reuse A row-tile through L2), y = row tiles
    gemm_bf16<0><<<dim3(D3 / 128, TOK / 128), 128, 2 * STAGE_B>>>(b_qkv, nullptr);
    attn_kernel<<<dim3(NM, NHE), 128>>>();
    gemm_bf16<1><<<dim3(DIM / 128, TOK / 128), 128, 2 * STAGE_B>>>(b_proj, out);
}

// round 8
// speedup vs baseline: 1.8490x; 1.8490x over previous
#include <cuda_runtime.h>
#include <cuda_bf16.h>
#include <cstdint>

#define NB   32
#define HW   48
#define DIM  384
#define D3   1152
#define NHE  8
#define HDI  48
#define WSZ  6
#define VTOK 36
#define NM   2048
#define TOK  73728
#define KDIM 384
#define SCALE 0.14433756729740643f

// ---------------- scratch (device globals) ----------------------------------
__device__ __nv_bfloat16 g_x_hi[(size_t)TOK * KDIM];
__device__ __nv_bfloat16 g_x_lo[(size_t)TOK * KDIM];
__device__ __nv_bfloat16 g_wq_hi[(size_t)D3 * KDIM];   // transposed [n][k]
__device__ __nv_bfloat16 g_wq_lo[(size_t)D3 * KDIM];
__device__ __nv_bfloat16 g_wp_hi[(size_t)DIM * KDIM];  // transposed [n][k]
__device__ __nv_bfloat16 g_wp_lo[(size_t)DIM * KDIM];
__device__ float         g_qkv[(size_t)TOK * D3];      // raster pixel order
__device__ __nv_bfloat16 g_att_hi[(size_t)TOK * DIM];  // raster pixel order
__device__ __nv_bfloat16 g_att_lo[(size_t)TOK * DIM];

__device__ __forceinline__ void split2(float v, uint16_t& h, uint16_t& l) {
    __nv_bfloat16 hb = __float2bfloat16_rn(v);
    float r = v - __bfloat162float(hb);
    __nv_bfloat16 lb = __float2bfloat16_rn(r);
    h = __bfloat16_as_ushort(hb);
    l = __bfloat16_as_ushort(lb);
}

// ---------------- prep kernels ----------------------------------------------
__global__ __launch_bounds__(256) void split_x(const float* __restrict__ x) {
    size_t i = (size_t)blockIdx.x * 256 + threadIdx.x;
    float4 v = ((const float4*)x)[i];
    uint16_t h0, h1, h2, h3, l0, l1, l2, l3;
    split2(v.x, h0, l0); split2(v.y, h1, l1);
    split2(v.z, h2, l2); split2(v.w, h3, l3);
    uint2 H, L;
    H.x = (uint32_t)h0 | ((uint32_t)h1 << 16);
    H.y = (uint32_t)h2 | ((uint32_t)h3 << 16);
    L.x = (uint32_t)l0 | ((uint32_t)l1 << 16);
    L.y = (uint32_t)l2 | ((uint32_t)l3 << 16);
    ((uint2*)g_x_hi)[i] = H;
    ((uint2*)g_x_lo)[i] = L;
}

template <int NT>
__global__ __launch_bounds__(256) void split_w(const float* __restrict__ w) {
    int idx = blockIdx.x * 256 + threadIdx.x;       // idx = k*NT + n
    int k = idx / NT, n = idx - k * NT;
    uint16_t h, l;
    split2(w[idx], h, l);
    __nv_bfloat16* wh = (NT == D3) ? g_wq_hi : g_wp_hi;
    __nv_bfloat16* wl = (NT == D3) ? g_wq_lo : g_wp_lo;
    ((uint16_t*)wh)[(size_t)n * KDIM + k] = h;
    ((uint16_t*)wl)[(size_t)n * KDIM + k] = l;
}

// ---------------- bf16-split tensor-core GEMM (R2 known-good) ---------------
#define SSTRIDE 40        // bf16 elements per smem row (32 data + 8 pad)
#define TILE_B  10240     // 128*40*2 bytes
#define STAGE_B 40960

__device__ __forceinline__ void cp16(uint32_t dst, const void* src) {
    asm volatile("cp.async.cg.shared.global [%0], [%1], 16;\n" :: "r"(dst), "l"(src));
}

#define MMA_BF16(d, a, b0, b1)                                                \
    asm volatile(                                                             \
        "mma.sync.aligned.m16n8k16.row.col.f32.bf16.bf16.f32 "                \
        "{%0,%1,%2,%3},{%4,%5,%6,%7},{%8,%9},{%0,%1,%2,%3};"                  \
        : "+f"(d[0]), "+f"(d[1]), "+f"(d[2]), "+f"(d[3])                      \
        : "r"(a[0]), "r"(a[1]), "r"(a[2]), "r"(a[3]), "r"(b0), "r"(b1))

__device__ __forceinline__ void stage_load(
    uint32_t sb, const __nv_bfloat16* __restrict__ Ah, const __nv_bfloat16* __restrict__ Al,
    const __nv_bfloat16* __restrict__ Bh, const __nv_bfloat16* __restrict__ Bl,
    int row0, int col0, int k0, int tid)
{
#pragma unroll
    for (int h2 = 0; h2 < 2; h2++) {
        int c = tid + h2 * 256;
        int r = c >> 2;
        int eo = (c & 3) * 8;
        uint32_t doff = (uint32_t)(r * SSTRIDE + eo) * 2;
        size_t aoff = (size_t)(row0 + r) * KDIM + k0 + eo;
        size_t boff = (size_t)(col0 + r) * KDIM + k0 + eo;
        cp16(sb + 0 * TILE_B + doff, Ah + aoff);
        cp16(sb + 1 * TILE_B + doff, Al + aoff);
        cp16(sb + 2 * TILE_B + doff, Bh + boff);
        cp16(sb + 3 * TILE_B + doff, Bl + boff);
    }
}

// WHICH: 0 = qkv, 1 = proj
template <int WHICH>
__global__ __launch_bounds__(256, 1) void gemm_bf16(const float* __restrict__ bias,
                                                    float* __restrict__ Cout)
{
    constexpr int NT = (WHICH == 0) ? D3 : DIM;
    const __nv_bfloat16* Ah = (WHICH == 0) ? g_x_hi : g_att_hi;
    const __nv_bfloat16* Al = (WHICH == 0) ? g_x_lo : g_att_lo;
    const __nv_bfloat16* Bh = (WHICH == 0) ? g_wq_hi : g_wp_hi;
    const __nv_bfloat16* Bl = (WHICH == 0) ? g_wq_lo : g_wp_lo;
    float* C = (WHICH == 0) ? g_qkv : Cout;

    extern __shared__ char sm[];
    const int tid  = threadIdx.x;
    const int row0 = blockIdx.x * 128;
    const int col0 = blockIdx.y * 128;
    const int lane = tid & 31, warp = tid >> 5;
    const int wm = warp & 1, wn = warp >> 1;      // 2 x 4 warp grid, warp tile 64x32
    const int g = lane >> 2, t = lane & 3;

    uint32_t sbase = (uint32_t)__cvta_generic_to_shared(sm);

    float acc[4][4][4] = {};

    stage_load(sbase, Ah, Al, Bh, Bl, row0, col0, 0, tid);
    asm volatile("cp.async.commit_group;\n" ::: "memory");

    for (int kt = 0; kt < 12; kt++) {
        if (kt < 11) {
            stage_load(sbase + ((kt + 1) & 1) * STAGE_B, Ah, Al, Bh, Bl,
                       row0, col0, (kt + 1) * 32, tid);
            asm volatile("cp.async.commit_group;\n" ::: "memory");
            asm volatile("cp.async.wait_group 1;\n" ::: "memory");
        } else {
            asm volatile("cp.async.wait_group 0;\n" ::: "memory");
        }
        __syncthreads();

        const __nv_bfloat16* sA_h = (const __nv_bfloat16*)(sm + (kt & 1) * STAGE_B);
        const __nv_bfloat16* sA_l = sA_h + 5120;
        const __nv_bfloat16* sB_h = sA_h + 10240;
        const __nv_bfloat16* sB_l = sA_h + 15360;

#pragma unroll
        for (int k16 = 0; k16 < 32; k16 += 16) {
            uint32_t ah[4][4], al[4][4], bh[4][2], bl[4][2];
#pragma unroll
            for (int mt = 0; mt < 4; mt++) {
                int e = (wm * 64 + mt * 16 + g) * SSTRIDE + k16 + t * 2;
                ah[mt][0] = *(const uint32_t*)(sA_h + e);
                ah[mt][1] = *(const uint32_t*)(sA_h + e + 8 * SSTRIDE);
                ah[mt][2] = *(const uint32_t*)(sA_h + e + 8);
                ah[mt][3] = *(const uint32_t*)(sA_h + e + 8 * SSTRIDE + 8);
                al[mt][0] = *(const uint32_t*)(sA_l + e);
                al[mt][1] = *(const uint32_t*)(sA_l + e + 8 * SSTRIDE);
                al[mt][2] = *(const uint32_t*)(sA_l + e + 8);
                al[mt][3] = *(const uint32_t*)(sA_l + e + 8 * SSTRIDE + 8);
            }
#pragma unroll
            for (int nt = 0; nt < 4; nt++) {
                int e = (wn * 32 + nt * 8 + g) * SSTRIDE + k16 + t * 2;
                bh[nt][0] = *(const uint32_t*)(sB_h + e);
                bh[nt][1] = *(const uint32_t*)(sB_h + e + 8);
                bl[nt][0] = *(const uint32_t*)(sB_l + e);
                bl[nt][1] = *(const uint32_t*)(sB_l + e + 8);
            }
#pragma unroll
            for (int mt = 0; mt < 4; mt++)
#pragma unroll
                for (int nt = 0; nt < 4; nt++)
                    MMA_BF16(acc[mt][nt], ah[mt], bh[nt][0], bh[nt][1]);
#pragma unroll
            for (int mt = 0; mt < 4; mt++)
#pragma unroll
                for (int nt = 0; nt < 4; nt++)
                    MMA_BF16(acc[mt][nt], ah[mt], bl[nt][0], bl[nt][1]);
#pragma unroll
            for (int mt = 0; mt < 4; mt++)
#pragma unroll
                for (int nt = 0; nt < 4; nt++)
                    MMA_BF16(acc[mt][nt], al[mt], bh[nt][0], bh[nt][1]);
        }
        __syncthreads();
    }

#pragma unroll
    for (int nt = 0; nt < 4; nt++) {
        int ce = col0 + wn * 32 + nt * 8 + t * 2;
        float b0 = bias[ce], b1 = bias[ce + 1];
#pragma unroll
        for (int mt = 0; mt < 4; mt++) {
            int re = row0 + wm * 64 + mt * 16 + g;
            float* p0 = C + (size_t)re * NT + ce;
            p0[0] = acc[mt][nt][0] + b0;
            p0[1] = acc[mt][nt][1] + b1;
            float* p1 = p0 + (size_t)8 * NT;
            p1[0] = acc[mt][nt][2] + b0;
            p1[1] = acc[mt][nt][3] + b1;
        }
    }
}

// ---------------- attention: register-tiled, quad-parallel softmax (R4-validated)
#define QS 52   // padded row stride (floats): conflict-free strided reads
__global__ __launch_bounds__(160) void attn_kernel() {
    const int m    = blockIdx.x;
    const int head = blockIdx.y;
    __shared__ float qs[VTOK][QS];
    __shared__ float ks[VTOK][QS];
    __shared__ float vs[VTOK][QS];
    __shared__ float ps[VTOK][VTOK];
    __shared__ int   rid[VTOK];
    __shared__ int   pix[VTOK];

    const int t = threadIdx.x;
    if (t < VTOK) {
        int wi = m & 63;
        int i  = (wi >> 3) * WSZ + t / WSZ;
        int j  = (wi & 7)  * WSZ + t % WSZ;
        rid[t] = ((i < 45) ? 2 : 0) + ((j < 45) ? 1 : 0);
        int b = m >> 6;
        int h = (i < 45) ? i + 3 : i - 45;
        int w = (j < 45) ? j + 3 : j - 45;
        pix[t] = (b * HW + h) * HW + w;
    }
    __syncthreads();

    for (int idx = t; idx < 3 * VTOK * 12; idx += 160) {
        int t3  = idx / (VTOK * 12);
        int rem = idx - t3 * (VTOK * 12);
        int r = rem / 12;
        int c = rem - r * 12;
        float4 f = *(const float4*)(g_qkv + (size_t)pix[r] * D3 + t3 * DIM + head * HDI + c * 4);
        float* dst = (t3 == 0) ? &qs[r][c * 4] : (t3 == 1) ? &ks[r][c * 4] : &vs[r][c * 4];
        *(float4*)dst = f;
    }
    __syncthreads();

    if (t < 144) {
        const int v = t >> 2, sub = t & 3, u0 = sub * 9;
        const unsigned mask = (t >= 128) ? 0x0000FFFFu : 0xFFFFFFFFu;
        float4 qv[12];
#pragma unroll
        for (int c = 0; c < 12; c++) qv[c] = *(float4*)&qs[v][c * 4];
        const int rv = rid[v];
        float s[9];
#pragma unroll
        for (int j = 0; j < 9; j++) {
            int u = u0 + j;
            float acc = 0.f;
#pragma unroll
            for (int c = 0; c < 12; c++) {
                float4 kv = *(float4*)&ks[u][c * 4];
                acc += qv[c].x * kv.x + qv[c].y * kv.y + qv[c].z * kv.z + qv[c].w * kv.w;
            }
            s[j] = (rv == rid[u]) ? acc * SCALE : -1e30f;
        }
        float mx = s[0];
#pragma unroll
        for (int j = 1; j < 9; j++) mx = fmaxf(mx, s[j]);
        mx = fmaxf(mx, __shfl_xor_sync(mask, mx, 1));
        mx = fmaxf(mx, __shfl_xor_sync(mask, mx, 2));
        float sum = 0.f;
#pragma unroll
        for (int j = 0; j < 9; j++) { s[j] = __expf(s[j] - mx); sum += s[j]; }
        sum += __shfl_xor_sync(mask, sum, 1);
        sum += __shfl_xor_sync(mask, sum, 2);
        float inv = 1.f / sum;
#pragma unroll
        for (int j = 0; j < 9; j++) ps[v][u0 + j] = s[j] * inv;
    }
    __syncthreads();

    if (t < 144) {
        const int v = t >> 2, dc = t & 3;   // 12-float strip of head dim
        float4 a0 = {0,0,0,0}, a1 = {0,0,0,0}, a2 = {0,0,0,0};
#pragma unroll 4
        for (int u = 0; u < VTOK; u++) {
            float p = ps[v][u];
            const float* vp = &vs[u][dc * 12];
            float4 v0 = *(const float4*)(vp);
            float4 v1 = *(const float4*)(vp + 4);
            float4 v2 = *(const float4*)(vp + 8);
            a0.x += p * v0.x; a0.y += p * v0.y; a0.z += p * v0.z; a0.w += p * v0.w;
            a1.x += p * v1.x; a1.y += p * v1.y; a1.z += p * v1.z; a1.w += p * v1.w;
            a2.x += p * v2.x; a2.y += p * v2.y; a2.z += p * v2.z; a2.w += p * v2.w;
        }
        float o[12] = {a0.x,a0.y,a0.z,a0.w,a1.x,a1.y,a1.z,a1.w,a2.x,a2.y,a2.z,a2.w};
        uint32_t H[6], L[6];
#pragma unroll
        for (int c = 0; c < 6; c++) {
            uint16_t h0, h1, l0, l1;
            split2(o[c * 2 + 0], h0, l0);
            split2(o[c * 2 + 1], h1, l1);
            H[c] = (uint32_t)h0 | ((uint32_t)h1 << 16);
            L[c] = (uint32_t)l0 | ((uint32_t)l1 << 16);
        }
        size_t off = (size_t)pix[v] * DIM + head * HDI + dc * 12;
        uint2* ph = (uint2*)(g_att_hi + off);
        uint2* pl = (uint2*)(g_att_lo + off);
        ph[0] = make_uint2(H[0], H[1]); ph[1] = make_uint2(H[2], H[3]); ph[2] = make_uint2(H[4], H[5]);
        pl[0] = make_uint2(L[0], L[1]); pl[1] = make_uint2(L[2], L[3]); pl[2] = make_uint2(L[4], L[5]);
    }
}

extern "C" void kernel_launch(void* const* d_in, const int* in_sizes, int n_in,
                              void* d_out, int out_size) {
    const float* x      = (const float*)d_in[0];
    const float* w_qkv  = (const float*)d_in[1];
    const float* b_qkv  = (const float*)d_in[2];
    const float* w_proj = (const float*)d_in[3];
    const float* b_proj = (const float*)d_in[4];
    float* out = (float*)d_out;

    cudaFuncSetAttribute(gemm_bf16<0>, cudaFuncAttributeMaxDynamicSharedMemorySize, 2 * STAGE_B);
    cudaFuncSetAttribute(gemm_bf16<1>, cudaFuncAttributeMaxDynamicSharedMemorySize, 2 * STAGE_B);

    split_x<<<27648, 256>>>(x);
    split_w<D3><<<(KDIM * D3) / 256, 256>>>(w_qkv);
    split_w<DIM><<<(KDIM * DIM) / 256, 256>>>(w_proj);

    gemm_bf16<0><<<dim3(TOK / 128, D3 / 128), 256, 2 * STAGE_B>>>(b_qkv, nullptr);
    attn_kernel<<<dim3(NM, NHE), 160>>>();
    gemm_bf16<1><<<dim3(TOK / 128, DIM / 128), 256, 2 * STAGE_B>>>(b_proj, out);
}

// round 12
// speedup vs baseline: 1.9983x; 1.0807x over previous
#include <cuda_runtime.h>
#include <cuda_bf16.h>
#include <cstdint>

#define NB   32
#define HW   48
#define DIM  384
#define D3   1152
#define NHE  8
#define HDI  48
#define WSZ  6
#define VTOK 36
#define NM   2048
#define TOK  73728
#define KDIM 384
#define SCALE 0.14433756729740643f

// ---------------- scratch (device globals) ----------------------------------
__device__ __nv_bfloat16 g_x_hi[(size_t)TOK * KDIM];
__device__ __nv_bfloat16 g_x_lo[(size_t)TOK * KDIM];
__device__ __nv_bfloat16 g_wq_hi[(size_t)D3 * KDIM];   // transposed [n][k]
__device__ __nv_bfloat16 g_wq_lo[(size_t)D3 * KDIM];
__device__ __nv_bfloat16 g_wp_hi[(size_t)DIM * KDIM];  // transposed [n][k]
__device__ __nv_bfloat16 g_wp_lo[(size_t)DIM * KDIM];
__device__ float         g_qkv[(size_t)TOK * D3];      // raster pixel order
__device__ __nv_bfloat16 g_att_hi[(size_t)TOK * DIM];  // raster pixel order
__device__ __nv_bfloat16 g_att_lo[(size_t)TOK * DIM];

__device__ __forceinline__ void split2(float v, uint16_t& h, uint16_t& l) {
    __nv_bfloat16 hb = __float2bfloat16_rn(v);
    float r = v - __bfloat162float(hb);
    __nv_bfloat16 lb = __float2bfloat16_rn(r);
    h = __bfloat16_as_ushort(hb);
    l = __bfloat16_as_ushort(lb);
}

// ---------------- prep kernels ----------------------------------------------
__global__ __launch_bounds__(256) void split_x(const float* __restrict__ x) {
    size_t i = (size_t)blockIdx.x * 256 + threadIdx.x;
    float4 v = ((const float4*)x)[i];
    uint16_t h0, h1, h2, h3, l0, l1, l2, l3;
    split2(v.x, h0, l0); split2(v.y, h1, l1);
    split2(v.z, h2, l2); split2(v.w, h3, l3);
    uint2 H, L;
    H.x = (uint32_t)h0 | ((uint32_t)h1 << 16);
    H.y = (uint32_t)h2 | ((uint32_t)h3 << 16);
    L.x = (uint32_t)l0 | ((uint32_t)l1 << 16);
    L.y = (uint32_t)l2 | ((uint32_t)l3 << 16);
    ((uint2*)g_x_hi)[i] = H;
    ((uint2*)g_x_lo)[i] = L;
}

template <int NT>
__global__ __launch_bounds__(256) void split_w(const float* __restrict__ w) {
    int idx = blockIdx.x * 256 + threadIdx.x;       // idx = k*NT + n
    int k = idx / NT, n = idx - k * NT;
    uint16_t h, l;
    split2(w[idx], h, l);
    __nv_bfloat16* wh = (NT == D3) ? g_wq_hi : g_wp_hi;
    __nv_bfloat16* wl = (NT == D3) ? g_wq_lo : g_wp_lo;
    ((uint16_t*)wh)[(size_t)n * KDIM + k] = h;
    ((uint16_t*)wl)[(size_t)n * KDIM + k] = l;
}

// ---------------- bf16-split tensor-core GEMM -------------------------------
#define SSTRIDE 40        // bf16 elements per smem row (32 data + 8 pad)
#define TILE_B  10240     // 128*40*2 bytes
#define STAGE_B 40960

__device__ __forceinline__ void cp16(uint32_t dst, const void* src) {
    asm volatile("cp.async.cg.shared.global [%0], [%1], 16;\n" :: "r"(dst), "l"(src));
}

#define MMA_BF16(d, a, b0, b1)                                                \
    asm volatile(                                                             \
        "mma.sync.aligned.m16n8k16.row.col.f32.bf16.bf16.f32 "                \
        "{%0,%1,%2,%3},{%4,%5,%6,%7},{%8,%9},{%0,%1,%2,%3};"                  \
        : "+f"(d[0]), "+f"(d[1]), "+f"(d[2]), "+f"(d[3])                      \
        : "r"(a[0]), "r"(a[1]), "r"(a[2]), "r"(a[3]), "r"(b0), "r"(b1))

__device__ __forceinline__ void stage_load(
    uint32_t sb, const __nv_bfloat16* __restrict__ Ah, const __nv_bfloat16* __restrict__ Al,
    const __nv_bfloat16* __restrict__ Bh, const __nv_bfloat16* __restrict__ Bl,
    int row0, int col0, int k0, int tid)
{
#pragma unroll
    for (int h2 = 0; h2 < 2; h2++) {
        int c = tid + h2 * 256;
        int r = c >> 2;
        int eo = (c & 3) * 8;
        uint32_t doff = (uint32_t)(r * SSTRIDE + eo) * 2;
        size_t aoff = (size_t)(row0 + r) * KDIM + k0 + eo;
        size_t boff = (size_t)(col0 + r) * KDIM + k0 + eo;
        cp16(sb + 0 * TILE_B + doff, Ah + aoff);
        cp16(sb + 1 * TILE_B + doff, Al + aoff);
        cp16(sb + 2 * TILE_B + doff, Bh + boff);
        cp16(sb + 3 * TILE_B + doff, Bl + boff);
    }
}

// WHICH: 0 = qkv, 1 = proj.  __launch_bounds__(256,2): cap regs at 128 so
// TWO CTAs co-reside per SM (smem 2x80KB fits) — the R8 kernel was
// latency-bound at 1 CTA/SM (occ 12.5%, nothing saturated).
template <int WHICH>
__global__ __launch_bounds__(256, 2) void gemm_bf16(const float* __restrict__ bias,
                                                    float* __restrict__ Cout)
{
    constexpr int NT = (WHICH == 0) ? D3 : DIM;
    const __nv_bfloat16* Ah = (WHICH == 0) ? g_x_hi : g_att_hi;
    const __nv_bfloat16* Al = (WHICH == 0) ? g_x_lo : g_att_lo;
    const __nv_bfloat16* Bh = (WHICH == 0) ? g_wq_hi : g_wp_hi;
    const __nv_bfloat16* Bl = (WHICH == 0) ? g_wq_lo : g_wp_lo;
    float* C = (WHICH == 0) ? g_qkv : Cout;

    extern __shared__ char sm[];
    const int tid  = threadIdx.x;
    const int row0 = blockIdx.x * 128;
    const int col0 = blockIdx.y * 128;
    const int lane = tid & 31, warp = tid >> 5;
    const int wm = warp & 1, wn = warp >> 1;      // 2 x 4 warp grid, warp tile 64x32
    const int g = lane >> 2, t = lane & 3;

    uint32_t sbase = (uint32_t)__cvta_generic_to_shared(sm);

    float acc[4][4][4] = {};

    stage_load(sbase, Ah, Al, Bh, Bl, row0, col0, 0, tid);
    asm volatile("cp.async.commit_group;\n" ::: "memory");

    for (int kt = 0; kt < 12; kt++) {
        if (kt < 11) {
            stage_load(sbase + ((kt + 1) & 1) * STAGE_B, Ah, Al, Bh, Bl,
                       row0, col0, (kt + 1) * 32, tid);
            asm volatile("cp.async.commit_group;\n" ::: "memory");
            asm volatile("cp.async.wait_group 1;\n" ::: "memory");
        } else {
            asm volatile("cp.async.wait_group 0;\n" ::: "memory");
        }
        __syncthreads();

        const __nv_bfloat16* sA_h = (const __nv_bfloat16*)(sm + (kt & 1) * STAGE_B);
        const __nv_bfloat16* sA_l = sA_h + 5120;
        const __nv_bfloat16* sB_h = sA_h + 10240;
        const __nv_bfloat16* sB_l = sA_h + 15360;

#pragma unroll
        for (int k16 = 0; k16 < 32; k16 += 16) {
            // Peak-pressure-aware schedule: ah/bh/bl live through passes 1-2,
            // al loaded only after ah dies (pass 3 uses al, bh).
            uint32_t ah[4][4], bh[4][2], bl[4][2];
#pragma unroll
            for (int mt = 0; mt < 4; mt++) {
                int e = (wm * 64 + mt * 16 + g) * SSTRIDE + k16 + t * 2;
                ah[mt][0] = *(const uint32_t*)(sA_h + e);
                ah[mt][1] = *(const uint32_t*)(sA_h + e + 8 * SSTRIDE);
                ah[mt][2] = *(const uint32_t*)(sA_h + e + 8);
                ah[mt][3] = *(const uint32_t*)(sA_h + e + 8 * SSTRIDE + 8);
            }
#pragma unroll
            for (int nt = 0; nt < 4; nt++) {
                int e = (wn * 32 + nt * 8 + g) * SSTRIDE + k16 + t * 2;
                bh[nt][0] = *(const uint32_t*)(sB_h + e);
                bh[nt][1] = *(const uint32_t*)(sB_h + e + 8);
                bl[nt][0] = *(const uint32_t*)(sB_l + e);
                bl[nt][1] = *(const uint32_t*)(sB_l + e + 8);
            }
#pragma unroll
            for (int mt = 0; mt < 4; mt++)
#pragma unroll
                for (int nt = 0; nt < 4; nt++)
                    MMA_BF16(acc[mt][nt], ah[mt], bh[nt][0], bh[nt][1]);
#pragma unroll
            for (int mt = 0; mt < 4; mt++)
#pragma unroll
                for (int nt = 0; nt < 4; nt++)
                    MMA_BF16(acc[mt][nt], ah[mt], bl[nt][0], bl[nt][1]);

            uint32_t al[4][4];
#pragma unroll
            for (int mt = 0; mt < 4; mt++) {
                int e = (wm * 64 + mt * 16 + g) * SSTRIDE + k16 + t * 2;
                al[mt][0] = *(const uint32_t*)(sA_l + e);
                al[mt][1] = *(const uint32_t*)(sA_l + e + 8 * SSTRIDE);
                al[mt][2] = *(const uint32_t*)(sA_l + e + 8);
                al[mt][3] = *(const uint32_t*)(sA_l + e + 8 * SSTRIDE + 8);
            }
#pragma unroll
            for (int mt = 0; mt < 4; mt++)
#pragma unroll
                for (int nt = 0; nt < 4; nt++)
                    MMA_BF16(acc[mt][nt], al[mt], bh[nt][0], bh[nt][1]);
        }
        __syncthreads();
    }

#pragma unroll
    for (int nt = 0; nt < 4; nt++) {
        int ce = col0 + wn * 32 + nt * 8 + t * 2;
        float b0 = bias[ce], b1 = bias[ce + 1];
#pragma unroll
        for (int mt = 0; mt < 4; mt++) {
            int re = row0 + wm * 64 + mt * 16 + g;
            float* p0 = C + (size_t)re * NT + ce;
            p0[0] = acc[mt][nt][0] + b0;
            p0[1] = acc[mt][nt][1] + b1;
            float* p1 = p0 + (size_t)8 * NT;
            p1[0] = acc[mt][nt][2] + b0;
            p1[1] = acc[mt][nt][3] + b1;
        }
    }
}

// ---------------- attention: register-tiled, quad-parallel softmax ----------
#define QS 52   // padded row stride (floats): conflict-free strided reads
__global__ __launch_bounds__(160) void attn_kernel() {
    const int m    = blockIdx.x;
    const int head = blockIdx.y;
    __shared__ float qs[VTOK][QS];
    __shared__ float ks[VTOK][QS];
    __shared__ float vs[VTOK][QS];
    __shared__ float ps[VTOK][VTOK];
    __shared__ int   rid[VTOK];
    __shared__ int   pix[VTOK];

    const int t = threadIdx.x;
    if (t < VTOK) {
        int wi = m & 63;
        int i  = (wi >> 3) * WSZ + t / WSZ;
        int j  = (wi & 7)  * WSZ + t % WSZ;
        rid[t] = ((i < 45) ? 2 : 0) + ((j < 45) ? 1 : 0);
        int b = m >> 6;
        int h = (i < 45) ? i + 3 : i - 45;
        int w = (j < 45) ? j + 3 : j - 45;
        pix[t] = (b * HW + h) * HW + w;
    }
    __syncthreads();

    for (int idx = t; idx < 3 * VTOK * 12; idx += 160) {
        int t3  = idx / (VTOK * 12);
        int rem = idx - t3 * (VTOK * 12);
        int r = rem / 12;
        int c = rem - r * 12;
        float4 f = *(const float4*)(g_qkv + (size_t)pix[r] * D3 + t3 * DIM + head * HDI + c * 4);
        float* dst = (t3 == 0) ? &qs[r][c * 4] : (t3 == 1) ? &ks[r][c * 4] : &vs[r][c * 4];
        *(float4*)dst = f;
    }
    __syncthreads();

    if (t < 144) {
        const int v = t >> 2, sub = t & 3, u0 = sub * 9;
        const unsigned mask = (t >= 128) ? 0x0000FFFFu : 0xFFFFFFFFu;
        float4 qv[12];
#pragma unroll
        for (int c = 0; c < 12; c++) qv[c] = *(float4*)&qs[v][c * 4];
        const int rv = rid[v];
        float s[9];
#pragma unroll
        for (int j = 0; j < 9; j++) {
            int u = u0 + j;
            float acc = 0.f;
#pragma unroll
            for (int c = 0; c < 12; c++) {
                float4 kv = *(float4*)&ks[u][c * 4];
                acc += qv[c].x * kv.x + qv[c].y * kv.y + qv[c].z * kv.z + qv[c].w * kv.w;
            }
            s[j] = (rv == rid[u]) ? acc * SCALE : -1e30f;
        }
        float mx = s[0];
#pragma unroll
        for (int j = 1; j < 9; j++) mx = fmaxf(mx, s[j]);
        mx = fmaxf(mx, __shfl_xor_sync(mask, mx, 1));
        mx = fmaxf(mx, __shfl_xor_sync(mask, mx, 2));
        float sum = 0.f;
#pragma unroll
        for (int j = 0; j < 9; j++) { s[j] = __expf(s[j] - mx); sum += s[j]; }
        sum += __shfl_xor_sync(mask, sum, 1);
        sum += __shfl_xor_sync(mask, sum, 2);
        float inv = 1.f / sum;
#pragma unroll
        for (int j = 0; j < 9; j++) ps[v][u0 + j] = s[j] * inv;
    }
    __syncthreads();

    if (t < 144) {
        const int v = t >> 2, dc = t & 3;   // 12-float strip of head dim
        float4 a0 = {0,0,0,0}, a1 = {0,0,0,0}, a2 = {0,0,0,0};
#pragma unroll 4
        for (int u = 0; u < VTOK; u++) {
            float p = ps[v][u];
            const float* vp = &vs[u][dc * 12];
            float4 v0 = *(const float4*)(vp);
            float4 v1 = *(const float4*)(vp + 4);
            float4 v2 = *(const float4*)(vp + 8);
            a0.x += p * v0.x; a0.y += p * v0.y; a0.z += p * v0.z; a0.w += p * v0.w;
            a1.x += p * v1.x; a1.y += p * v1.y; a1.z += p * v1.z; a1.w += p * v1.w;
            a2.x += p * v2.x; a2.y += p * v2.y; a2.z += p * v2.z; a2.w += p * v2.w;
        }
        float o[12] = {a0.x,a0.y,a0.z,a0.w,a1.x,a1.y,a1.z,a1.w,a2.x,a2.y,a2.z,a2.w};
        uint32_t H[6], L[6];
#pragma unroll
        for (int c = 0; c < 6; c++) {
            uint16_t h0, h1, l0, l1;
            split2(o[c * 2 + 0], h0, l0);
            split2(o[c * 2 + 1], h1, l1);
            H[c] = (uint32_t)h0 | ((uint32_t)h1 << 16);
            L[c] = (uint32_t)l0 | ((uint32_t)l1 << 16);
        }
        size_t off = (size_t)pix[v] * DIM + head * HDI + dc * 12;
        uint2* ph = (uint2*)(g_att_hi + off);
        uint2* pl = (uint2*)(g_att_lo + off);
        ph[0] = make_uint2(H[0], H[1]); ph[1] = make_uint2(H[2], H[3]); ph[2] = make_uint2(H[4], H[5]);
        pl[0] = make_uint2(L[0], L[1]); pl[1] = make_uint2(L[2], L[3]); pl[2] = make_uint2(L[4], L[5]);
    }
}

extern "C" void kernel_launch(void* const* d_in, const int* in_sizes, int n_in,
                              void* d_out, int out_size) {
    const float* x      = (const float*)d_in[0];
    const float* w_qkv  = (const float*)d_in[1];
    const float* b_qkv  = (const float*)d_in[2];
    const float* w_proj = (const float*)d_in[3];
    const float* b_proj = (const float*)d_in[4];
    float* out = (float*)d_out;

    cudaFuncSetAttribute(gemm_bf16<0>, cudaFuncAttributeMaxDynamicSharedMemorySize, 2 * STAGE_B);
    cudaFuncSetAttribute(gemm_bf16<1>, cudaFuncAttributeMaxDynamicSharedMemorySize, 2 * STAGE_B);

    split_x<<<27648, 256>>>(x);
    split_w<D3><<<(KDIM * D3) / 256, 256>>>(w_qkv);
    split_w<DIM><<<(KDIM * DIM) / 256, 256>>>(w_proj);

    gemm_bf16<0><<<dim3(TOK / 128, D3 / 128), 256, 2 * STAGE_B>>>(b_qkv, nullptr);
    attn_kernel<<<dim3(NM, NHE), 160>>>();
    gemm_bf16<1><<<dim3(TOK / 128, DIM / 128), 256, 2 * STAGE_B>>>(b_proj, out);
}

// round 13
// speedup vs baseline: 3.1381x; 1.5704x over previous
#include <cuda_runtime.h>
#include <cuda_fp16.h>
#include <cstdint>

#define NB   32
#define HW   48
#define DIM  384
#define D3   1152
#define NHE  8
#define HDI  48
#define WSZ  6
#define VTOK 36
#define NM   2048
#define TOK  73728
#define KDIM 384
#define SCALE 0.14433756729740643f

// ---------------- scratch (device globals) ----------------------------------
__device__ __half g_x_h[(size_t)TOK * KDIM];
__device__ __half g_wq_h[(size_t)D3 * KDIM];    // transposed [n][k]
__device__ __half g_wp_h[(size_t)DIM * KDIM];   // transposed [n][k]
__device__ float  g_qkv[(size_t)TOK * D3];      // raster pixel order
__device__ __half g_att_h[(size_t)TOK * DIM];   // raster pixel order

// ---------------- prep kernels ----------------------------------------------
__global__ __launch_bounds__(256) void conv_x(const float* __restrict__ x) {
    size_t i = (size_t)blockIdx.x * 256 + threadIdx.x;
    float4 v = ((const float4*)x)[i];
    uint32_t p0 = (uint32_t)__half_as_ushort(__float2half_rn(v.x)) |
                  ((uint32_t)__half_as_ushort(__float2half_rn(v.y)) << 16);
    uint32_t p1 = (uint32_t)__half_as_ushort(__float2half_rn(v.z)) |
                  ((uint32_t)__half_as_ushort(__float2half_rn(v.w)) << 16);
    ((uint2*)g_x_h)[i] = make_uint2(p0, p1);
}

template <int NT>
__global__ __launch_bounds__(256) void conv_w(const float* __restrict__ w) {
    int idx = blockIdx.x * 256 + threadIdx.x;       // idx = k*NT + n
    int k = idx / NT, n = idx - k * NT;
    __half* wh = (NT == D3) ? g_wq_h : g_wp_h;
    wh[(size_t)n * KDIM + k] = __float2half_rn(w[idx]);
}

// ---------------- fp16 tensor-core GEMM --------------------------------------
#define SSTRIDE 40        // half elements per smem row (32 data + 8 pad)
#define TILE_B  10240     // 128*40*2 bytes
#define STAGE_B 20480     // A | B

__device__ __forceinline__ void cp16(uint32_t dst, const void* src) {
    asm volatile("cp.async.cg.shared.global [%0], [%1], 16;\n" :: "r"(dst), "l"(src));
}

#define MMA_F16(d, a, b0, b1)                                                 \
    asm volatile(                                                             \
        "mma.sync.aligned.m16n8k16.row.col.f32.f16.f16.f32 "                  \
        "{%0,%1,%2,%3},{%4,%5,%6,%7},{%8,%9},{%0,%1,%2,%3};"                  \
        : "+f"(d[0]), "+f"(d[1]), "+f"(d[2]), "+f"(d[3])                      \
        : "r"(a[0]), "r"(a[1]), "r"(a[2]), "r"(a[3]), "r"(b0), "r"(b1))

__device__ __forceinline__ void stage_load(
    uint32_t sb, const __half* __restrict__ A, const __half* __restrict__ B,
    int row0, int col0, int k0, int tid)
{
#pragma unroll
    for (int h2 = 0; h2 < 2; h2++) {
        int c = tid + h2 * 256;
        int r = c >> 2;
        int eo = (c & 3) * 8;
        uint32_t doff = (uint32_t)(r * SSTRIDE + eo) * 2;
        cp16(sb + 0 * TILE_B + doff, A + (size_t)(row0 + r) * KDIM + k0 + eo);
        cp16(sb + 1 * TILE_B + doff, B + (size_t)(col0 + r) * KDIM + k0 + eo);
    }
}

// WHICH: 0 = qkv, 1 = proj.  2 CTAs/SM (regs<=128, smem 2x40KB).
template <int WHICH>
__global__ __launch_bounds__(256, 2) void gemm_f16(const float* __restrict__ bias,
                                                   float* __restrict__ Cout)
{
    constexpr int NT = (WHICH == 0) ? D3 : DIM;
    const __half* A = (WHICH == 0) ? g_x_h : g_att_h;
    const __half* B = (WHICH == 0) ? g_wq_h : g_wp_h;
    float* C = (WHICH == 0) ? g_qkv : Cout;

    extern __shared__ char sm[];
    const int tid  = threadIdx.x;
    const int row0 = blockIdx.x * 128;
    const int col0 = blockIdx.y * 128;
    const int lane = tid & 31, warp = tid >> 5;
    const int wm = warp & 1, wn = warp >> 1;      // 2 x 4 warp grid, warp tile 64x32
    const int g = lane >> 2, t = lane & 3;

    uint32_t sbase = (uint32_t)__cvta_generic_to_shared(sm);

    float acc[4][4][4] = {};

    stage_load(sbase, A, B, row0, col0, 0, tid);
    asm volatile("cp.async.commit_group;\n" ::: "memory");

    for (int kt = 0; kt < 12; kt++) {
        if (kt < 11) {
            stage_load(sbase + ((kt + 1) & 1) * STAGE_B, A, B,
                       row0, col0, (kt + 1) * 32, tid);
            asm volatile("cp.async.commit_group;\n" ::: "memory");
            asm volatile("cp.async.wait_group 1;\n" ::: "memory");
        } else {
            asm volatile("cp.async.wait_group 0;\n" ::: "memory");
        }
        __syncthreads();

        const __half* sA = (const __half*)(sm + (kt & 1) * STAGE_B);
        const __half* sB = sA + 5120;

#pragma unroll
        for (int k16 = 0; k16 < 32; k16 += 16) {
            uint32_t ah[4][4], bh[4][2];
#pragma unroll
            for (int mt = 0; mt < 4; mt++) {
                int e = (wm * 64 + mt * 16 + g) * SSTRIDE + k16 + t * 2;
                ah[mt][0] = *(const uint32_t*)(sA + e);
                ah[mt][1] = *(const uint32_t*)(sA + e + 8 * SSTRIDE);
                ah[mt][2] = *(const uint32_t*)(sA + e + 8);
                ah[mt][3] = *(const uint32_t*)(sA + e + 8 * SSTRIDE + 8);
            }
#pragma unroll
            for (int nt = 0; nt < 4; nt++) {
                int e = (wn * 32 + nt * 8 + g) * SSTRIDE + k16 + t * 2;
                bh[nt][0] = *(const uint32_t*)(sB + e);
                bh[nt][1] = *(const uint32_t*)(sB + e + 8);
            }
#pragma unroll
            for (int mt = 0; mt < 4; mt++)
#pragma unroll
                for (int nt = 0; nt < 4; nt++)
                    MMA_F16(acc[mt][nt], ah[mt], bh[nt][0], bh[nt][1]);
        }
        __syncthreads();
    }

#pragma unroll
    for (int nt = 0; nt < 4; nt++) {
        int ce = col0 + wn * 32 + nt * 8 + t * 2;
        float b0 = bias[ce], b1 = bias[ce + 1];
#pragma unroll
        for (int mt = 0; mt < 4; mt++) {
            int re = row0 + wm * 64 + mt * 16 + g;
            float* p0 = C + (size_t)re * NT + ce;
            p0[0] = acc[mt][nt][0] + b0;
            p0[1] = acc[mt][nt][1] + b1;
            float* p1 = p0 + (size_t)8 * NT;
            p1[0] = acc[mt][nt][2] + b0;
            p1[1] = acc[mt][nt][3] + b1;
        }
    }
}

// ---------------- attention: register-tiled, quad-parallel softmax ----------
#define QS 52   // padded row stride (floats): conflict-free strided reads
__global__ __launch_bounds__(160) void attn_kernel() {
    const int m    = blockIdx.x;
    const int head = blockIdx.y;
    __shared__ float qs[VTOK][QS];
    __shared__ float ks[VTOK][QS];
    __shared__ float vs[VTOK][QS];
    __shared__ float ps[VTOK][VTOK];
    __shared__ int   rid[VTOK];
    __shared__ int   pix[VTOK];

    const int t = threadIdx.x;
    if (t < VTOK) {
        int wi = m & 63;
        int i  = (wi >> 3) * WSZ + t / WSZ;
        int j  = (wi & 7)  * WSZ + t % WSZ;
        rid[t] = ((i < 45) ? 2 : 0) + ((j < 45) ? 1 : 0);
        int b = m >> 6;
        int h = (i < 45) ? i + 3 : i - 45;
        int w = (j < 45) ? j + 3 : j - 45;
        pix[t] = (b * HW + h) * HW + w;
    }
    __syncthreads();

    for (int idx = t; idx < 3 * VTOK * 12; idx += 160) {
        int t3  = idx / (VTOK * 12);
        int rem = idx - t3 * (VTOK * 12);
        int r = rem / 12;
        int c = rem - r * 12;
        float4 f = *(const float4*)(g_qkv + (size_t)pix[r] * D3 + t3 * DIM + head * HDI + c * 4);
        float* dst = (t3 == 0) ? &qs[r][c * 4] : (t3 == 1) ? &ks[r][c * 4] : &vs[r][c * 4];
        *(float4*)dst = f;
    }
    __syncthreads();

    if (t < 144) {
        const int v = t >> 2, sub = t & 3, u0 = sub * 9;
        const unsigned mask = (t >= 128) ? 0x0000FFFFu : 0xFFFFFFFFu;
        float4 qv[12];
#pragma unroll
        for (int c = 0; c < 12; c++) qv[c] = *(float4*)&qs[v][c * 4];
        const int rv = rid[v];
        float s[9];
#pragma unroll
        for (int j = 0; j < 9; j++) {
            int u = u0 + j;
            float acc = 0.f;
#pragma unroll
            for (int c = 0; c < 12; c++) {
                float4 kv = *(float4*)&ks[u][c * 4];
                acc += qv[c].x * kv.x + qv[c].y * kv.y + qv[c].z * kv.z + qv[c].w * kv.w;
            }
            s[j] = (rv == rid[u]) ? acc * SCALE : -1e30f;
        }
        float mx = s[0];
#pragma unroll
        for (int j = 1; j < 9; j++) mx = fmaxf(mx, s[j]);
        mx = fmaxf(mx, __shfl_xor_sync(mask, mx, 1));
        mx = fmaxf(mx, __shfl_xor_sync(mask, mx, 2));
        float sum = 0.f;
#pragma unroll
        for (int j = 0; j < 9; j++) { s[j] = __expf(s[j] - mx); sum += s[j]; }
        sum += __shfl_xor_sync(mask, sum, 1);
        sum += __shfl_xor_sync(mask, sum, 2);
        float inv = 1.f / sum;
#pragma unroll
        for (int j = 0; j < 9; j++) ps[v][u0 + j] = s[j] * inv;
    }
    __syncthreads();

    if (t < 144) {
        const int v = t >> 2, dc = t & 3;   // 12-float strip of head dim
        float4 a0 = {0,0,0,0}, a1 = {0,0,0,0}, a2 = {0,0,0,0};
#pragma unroll 4
        for (int u = 0; u < VTOK; u++) {
            float p = ps[v][u];
            const float* vp = &vs[u][dc * 12];
            float4 v0 = *(const float4*)(vp);
            float4 v1 = *(const float4*)(vp + 4);
            float4 v2 = *(const float4*)(vp + 8);
            a0.x += p * v0.x; a0.y += p * v0.y; a0.z += p * v0.z; a0.w += p * v0.w;
            a1.x += p * v1.x; a1.y += p * v1.y; a1.z += p * v1.z; a1.w += p * v1.w;
            a2.x += p * v2.x; a2.y += p * v2.y; a2.z += p * v2.z; a2.w += p * v2.w;
        }
        float o[12] = {a0.x,a0.y,a0.z,a0.w,a1.x,a1.y,a1.z,a1.w,a2.x,a2.y,a2.z,a2.w};
        uint32_t P[6];
#pragma unroll
        for (int c = 0; c < 6; c++) {
            P[c] = (uint32_t)__half_as_ushort(__float2half_rn(o[c * 2 + 0])) |
                   ((uint32_t)__half_as_ushort(__float2half_rn(o[c * 2 + 1])) << 16);
        }
        size_t off = (size_t)pix[v] * DIM + head * HDI + dc * 12;
        uint2* ph = (uint2*)(g_att_h + off);
        ph[0] = make_uint2(P[0], P[1]);
        ph[1] = make_uint2(P[2], P[3]);
        ph[2] = make_uint2(P[4], P[5]);
    }
}

extern "C" void kernel_launch(void* const* d_in, const int* in_sizes, int n_in,
                              void* d_out, int out_size) {
    const float* x      = (const float*)d_in[0];
    const float* w_qkv  = (const float*)d_in[1];
    const float* b_qkv  = (const float*)d_in[2];
    const float* w_proj = (const float*)d_in[3];
    const float* b_proj = (const float*)d_in[4];
    float* out = (float*)d_out;

    cudaFuncSetAttribute(gemm_f16<0>, cudaFuncAttributeMaxDynamicSharedMemorySize, 2 * STAGE_B);
    cudaFuncSetAttribute(gemm_f16<1>, cudaFuncAttributeMaxDynamicSharedMemorySize, 2 * STAGE_B);

    conv_x<<<27648, 256>>>(x);
    conv_w<D3><<<(KDIM * D3) / 256, 256>>>(w_qkv);
    conv_w<DIM><<<(KDIM * DIM) / 256, 256>>>(w_proj);

    gemm_f16<0><<<dim3(TOK / 128, D3 / 128), 256, 2 * STAGE_B>>>(b_qkv, nullptr);
    attn_kernel<<<dim3(NM, NHE), 160>>>();
    gemm_f16<1><<<dim3(TOK / 128, DIM / 128), 256, 2 * STAGE_B>>>(b_proj, out);
}

// round 14
// speedup vs baseline: 3.2654x; 1.0406x over previous
#include <cuda_runtime.h>
#include <cuda_fp16.h>
#include <cstdint>

#define NB   32
#define HW   48
#define DIM  384
#define D3   1152
#define NHE  8
#define HDI  48
#define WSZ  6
#define VTOK 36
#define NM   2048
#define TOK  73728
#define KDIM 384
#define SCALE 0.14433756729740643f

// ---------------- scratch (device globals) ----------------------------------
__device__ __half g_x_h[(size_t)TOK * KDIM];
__device__ __half g_wq_h[(size_t)D3 * KDIM];    // transposed [n][k]
__device__ __half g_wp_h[(size_t)DIM * KDIM];   // transposed [n][k]
__device__ float  g_qkv[(size_t)TOK * D3];      // raster pixel order
__device__ __half g_att_h[(size_t)TOK * DIM];   // raster pixel order

// ---------------- prep kernels ----------------------------------------------
__global__ __launch_bounds__(256) void conv_x(const float* __restrict__ x) {
    size_t i = (size_t)blockIdx.x * 256 + threadIdx.x;
    float4 v = ((const float4*)x)[i];
    uint32_t p0 = (uint32_t)__half_as_ushort(__float2half_rn(v.x)) |
                  ((uint32_t)__half_as_ushort(__float2half_rn(v.y)) << 16);
    uint32_t p1 = (uint32_t)__half_as_ushort(__float2half_rn(v.z)) |
                  ((uint32_t)__half_as_ushort(__float2half_rn(v.w)) << 16);
    ((uint2*)g_x_h)[i] = make_uint2(p0, p1);
}

template <int NT>
__global__ __launch_bounds__(256) void conv_w(const float* __restrict__ w) {
    int idx = blockIdx.x * 256 + threadIdx.x;       // idx = k*NT + n
    int k = idx / NT, n = idx - k * NT;
    __half* wh = (NT == D3) ? g_wq_h : g_wp_h;
    wh[(size_t)n * KDIM + k] = __float2half_rn(w[idx]);
}

// ---------------- fp16 tensor-core GEMM --------------------------------------
// CTA 128x128, 128 threads = 4 warps in 2x2 grid, warp tile 64x64
// (LDS/MMA = 1.0 vs 1.5 for 64x32). 2 CTAs/SM (256-reg budget, smem 2x80KB).
// 4-stage cp.async ring hides L2/DRAM latency.
#define SSTRIDE 40        // half elements per smem row (32 data + 8 pad)
#define TILE_B  10240     // 128*40*2 bytes
#define STAGE_B 20480     // A | B
#define NSTAGES 4

__device__ __forceinline__ void cp16(uint32_t dst, const void* src) {
    asm volatile("cp.async.cg.shared.global [%0], [%1], 16;\n" :: "r"(dst), "l"(src));
}

#define MMA_F16(d, a, b0, b1)                                                 \
    asm volatile(                                                             \
        "mma.sync.aligned.m16n8k16.row.col.f32.f16.f16.f32 "                  \
        "{%0,%1,%2,%3},{%4,%5,%6,%7},{%8,%9},{%0,%1,%2,%3};"                  \
        : "+f"(d[0]), "+f"(d[1]), "+f"(d[2]), "+f"(d[3])                      \
        : "r"(a[0]), "r"(a[1]), "r"(a[2]), "r"(a[3]), "r"(b0), "r"(b1))

__device__ __forceinline__ void stage_load(
    uint32_t sb, const __half* __restrict__ A, const __half* __restrict__ B,
    int row0, int col0, int k0, int tid)
{
#pragma unroll
    for (int i = 0; i < 8; i++) {
        int c = tid + i * 128;                      // 0..1023
        int half_ = c >> 9;                         // 0=A, 1=B
        int w = c & 511;
        int r = w >> 2;
        int eo = (w & 3) * 8;
        uint32_t doff = half_ * TILE_B + (uint32_t)(r * SSTRIDE + eo) * 2;
        const __half* src = half_ ? B : A;
        int rb = half_ ? col0 : row0;
        cp16(sb + doff, src + (size_t)(rb + r) * KDIM + k0 + eo);
    }
    asm volatile("cp.async.commit_group;\n" ::: "memory");
}

// WHICH: 0 = qkv, 1 = proj.
template <int WHICH>
__global__ __launch_bounds__(128, 2) void gemm_f16(const float* __restrict__ bias,
                                                   float* __restrict__ Cout)
{
    constexpr int NT = (WHICH == 0) ? D3 : DIM;
    const __half* A = (WHICH == 0) ? g_x_h : g_att_h;
    const __half* B = (WHICH == 0) ? g_wq_h : g_wp_h;
    float* C = (WHICH == 0) ? g_qkv : Cout;

    extern __shared__ char sm[];
    const int tid  = threadIdx.x;
    const int row0 = blockIdx.x * 128;
    const int col0 = blockIdx.y * 128;
    const int lane = tid & 31, warp = tid >> 5;
    const int wm = warp & 1, wn = warp >> 1;      // 2x2 warp grid, tile 64x64
    const int g = lane >> 2, t = lane & 3;

    uint32_t sbase = (uint32_t)__cvta_generic_to_shared(sm);

    float acc[4][8][4] = {};

    stage_load(sbase + 0 * STAGE_B, A, B, row0, col0, 0, tid);
    stage_load(sbase + 1 * STAGE_B, A, B, row0, col0, 32, tid);
    stage_load(sbase + 2 * STAGE_B, A, B, row0, col0, 64, tid);

    for (int kt = 0; kt < 12; kt++) {
        if (kt + 3 < 12) {
            stage_load(sbase + ((kt + 3) & 3) * STAGE_B, A, B,
                       row0, col0, (kt + 3) * 32, tid);
            asm volatile("cp.async.wait_group 3;\n" ::: "memory");
        } else if (kt + 3 == 12) {
            asm volatile("cp.async.wait_group 2;\n" ::: "memory");
        } else if (kt + 3 == 13) {
            asm volatile("cp.async.wait_group 1;\n" ::: "memory");
        } else {
            asm volatile("cp.async.wait_group 0;\n" ::: "memory");
        }
        __syncthreads();

        const __half* sA = (const __half*)(sm + (kt & 3) * STAGE_B);
        const __half* sB = sA + 5120;

#pragma unroll
        for (int k16 = 0; k16 < 32; k16 += 16) {
            uint32_t ah[4][4], bh[8][2];
#pragma unroll
            for (int mt = 0; mt < 4; mt++) {
                int e = (wm * 64 + mt * 16 + g) * SSTRIDE + k16 + t * 2;
                ah[mt][0] = *(const uint32_t*)(sA + e);
                ah[mt][1] = *(const uint32_t*)(sA + e + 8 * SSTRIDE);
                ah[mt][2] = *(const uint32_t*)(sA + e + 8);
                ah[mt][3] = *(const uint32_t*)(sA + e + 8 * SSTRIDE + 8);
            }
#pragma unroll
            for (int nt = 0; nt < 8; nt++) {
                int e = (wn * 64 + nt * 8 + g) * SSTRIDE + k16 + t * 2;
                bh[nt][0] = *(const uint32_t*)(sB + e);
                bh[nt][1] = *(const uint32_t*)(sB + e + 8);
            }
#pragma unroll
            for (int mt = 0; mt < 4; mt++)
#pragma unroll
                for (int nt = 0; nt < 8; nt++)
                    MMA_F16(acc[mt][nt], ah[mt], bh[nt][0], bh[nt][1]);
        }
        __syncthreads();
    }

#pragma unroll
    for (int nt = 0; nt < 8; nt++) {
        int ce = col0 + wn * 64 + nt * 8 + t * 2;
        float b0 = bias[ce], b1 = bias[ce + 1];
#pragma unroll
        for (int mt = 0; mt < 4; mt++) {
            int re = row0 + wm * 64 + mt * 16 + g;
            float* p0 = C + (size_t)re * NT + ce;
            p0[0] = acc[mt][nt][0] + b0;
            p0[1] = acc[mt][nt][1] + b1;
            float* p1 = p0 + (size_t)8 * NT;
            p1[0] = acc[mt][nt][2] + b0;
            p1[1] = acc[mt][nt][3] + b1;
        }
    }
}

// ---------------- attention: register-tiled, quad-parallel softmax ----------
#define QS 52   // padded row stride (floats): conflict-free strided reads
__global__ __launch_bounds__(160) void attn_kernel() {
    const int m    = blockIdx.x;
    const int head = blockIdx.y;
    __shared__ float qs[VTOK][QS];
    __shared__ float ks[VTOK][QS];
    __shared__ float vs[VTOK][QS];
    __shared__ float ps[VTOK][VTOK];
    __shared__ int   rid[VTOK];
    __shared__ int   pix[VTOK];

    const int t = threadIdx.x;
    if (t < VTOK) {
        int wi = m & 63;
        int i  = (wi >> 3) * WSZ + t / WSZ;
        int j  = (wi & 7)  * WSZ + t % WSZ;
        rid[t] = ((i < 45) ? 2 : 0) + ((j < 45) ? 1 : 0);
        int b = m >> 6;
        int h = (i < 45) ? i + 3 : i - 45;
        int w = (j < 45) ? j + 3 : j - 45;
        pix[t] = (b * HW + h) * HW + w;
    }
    __syncthreads();

    for (int idx = t; idx < 3 * VTOK * 12; idx += 160) {
        int t3  = idx / (VTOK * 12);
        int rem = idx - t3 * (VTOK * 12);
        int r = rem / 12;
        int c = rem - r * 12;
        float4 f = *(const float4*)(g_qkv + (size_t)pix[r] * D3 + t3 * DIM + head * HDI + c * 4);
        float* dst = (t3 == 0) ? &qs[r][c * 4] : (t3 == 1) ? &ks[r][c * 4] : &vs[r][c * 4];
        *(float4*)dst = f;
    }
    __syncthreads();

    if (t < 144) {
        const int v = t >> 2, sub = t & 3, u0 = sub * 9;
        const unsigned mask = (t >= 128) ? 0x0000FFFFu : 0xFFFFFFFFu;
        float4 qv[12];
#pragma unroll
        for (int c = 0; c < 12; c++) qv[c] = *(float4*)&qs[v][c * 4];
        const int rv = rid[v];
        float s[9];
#pragma unroll
        for (int j = 0; j < 9; j++) {
            int u = u0 + j;
            float acc = 0.f;
#pragma unroll
            for (int c = 0; c < 12; c++) {
                float4 kv = *(float4*)&ks[u][c * 4];
                acc += qv[c].x * kv.x + qv[c].y * kv.y + qv[c].z * kv.z + qv[c].w * kv.w;
            }
            s[j] = (rv == rid[u]) ? acc * SCALE : -1e30f;
        }
        float mx = s[0];
#pragma unroll
        for (int j = 1; j < 9; j++) mx = fmaxf(mx, s[j]);
        mx = fmaxf(mx, __shfl_xor_sync(mask, mx, 1));
        mx = fmaxf(mx, __shfl_xor_sync(mask, mx, 2));
        float sum = 0.f;
#pragma unroll
        for (int j = 0; j < 9; j++) { s[j] = __expf(s[j] - mx); sum += s[j]; }
        sum += __shfl_xor_sync(mask, sum, 1);
        sum += __shfl_xor_sync(mask, sum, 2);
        float inv = 1.f / sum;
#pragma unroll
        for (int j = 0; j < 9; j++) ps[v][u0 + j] = s[j] * inv;
    }
    __syncthreads();

    if (t < 144) {
        const int v = t >> 2, dc = t & 3;   // 12-float strip of head dim
        float4 a0 = {0,0,0,0}, a1 = {0,0,0,0}, a2 = {0,0,0,0};
#pragma unroll 4
        for (int u = 0; u < VTOK; u++) {
            float p = ps[v][u];
            const float* vp = &vs[u][dc * 12];
            float4 v0 = *(const float4*)(vp);
            float4 v1 = *(const float4*)(vp + 4);
            float4 v2 = *(const float4*)(vp + 8);
            a0.x += p * v0.x; a0.y += p * v0.y; a0.z += p * v0.z; a0.w += p * v0.w;
            a1.x += p * v1.x; a1.y += p * v1.y; a1.z += p * v1.z; a1.w += p * v1.w;
            a2.x += p * v2.x; a2.y += p * v2.y; a2.z += p * v2.z; a2.w += p * v2.w;
        }
        float o[12] = {a0.x,a0.y,a0.z,a0.w,a1.x,a1.y,a1.z,a1.w,a2.x,a2.y,a2.z,a2.w};
        uint32_t P[6];
#pragma unroll
        for (int c = 0; c < 6; c++) {
            P[c] = (uint32_t)__half_as_ushort(__float2half_rn(o[c * 2 + 0])) |
                   ((uint32_t)__half_as_ushort(__float2half_rn(o[c * 2 + 1])) << 16);
        }
        size_t off = (size_t)pix[v] * DIM + head * HDI + dc * 12;
        uint2* ph = (uint2*)(g_att_h + off);
        ph[0] = make_uint2(P[0], P[1]);
        ph[1] = make_uint2(P[2], P[3]);
        ph[2] = make_uint2(P[4], P[5]);
    }
}

extern "C" void kernel_launch(void* const* d_in, const int* in_sizes, int n_in,
                              void* d_out, int out_size) {
    const float* x      = (const float*)d_in[0];
    const float* w_qkv  = (const float*)d_in[1];
    const float* b_qkv  = (const float*)d_in[2];
    const float* w_proj = (const float*)d_in[3];
    const float* b_proj = (const float*)d_in[4];
    float* out = (float*)d_out;

    cudaFuncSetAttribute(gemm_f16<0>, cudaFuncAttributeMaxDynamicSharedMemorySize, NSTAGES * STAGE_B);
    cudaFuncSetAttribute(gemm_f16<1>, cudaFuncAttributeMaxDynamicSharedMemorySize, NSTAGES * STAGE_B);

    conv_x<<<27648, 256>>>(x);
    conv_w<D3><<<(KDIM * D3) / 256, 256>>>(w_qkv);
    conv_w<DIM><<<(KDIM * DIM) / 256, 256>>>(w_proj);

    gemm_f16<0><<<dim3(TOK / 128, D3 / 128), 128, NSTAGES * STAGE_B>>>(b_qkv, nullptr);
    attn_kernel<<<dim3(NM, NHE), 160>>>();
    gemm_f16<1><<<dim3(TOK / 128, DIM / 128), 128, NSTAGES * STAGE_B>>>(b_proj, out);
}